// round 8
// baseline (speedup 1.0000x reference)
#include <cuda_runtime.h>
#include <cstdint>

#define SEQ 128
#define BATCH 256
#define N_IN 1024
#define N_ST 256

// ---------------- static device scratch (no allocations allowed) ----------------
__device__ uint32_t g_inp[SEQ * BATCH * 8];     // packed input bits: [t][b][8 words]
__device__ uint32_t g_memA[N_IN * 2048];        // packed input-layer RAM: [n][2048 words]
__device__ uint32_t g_memB[N_ST * 2048];        // packed state-layer RAM
__device__ uint32_t g_connA[N_IN * 16];         // (shift<<16) | byte_offset_into_rep
__device__ uint32_t g_connB[N_ST * 16];

// Pack 32 float32 {0.0,1.0} elements -> one 32-bit word (bit j = elem j != 0).
__global__ void pack_f32_kernel(const float* __restrict__ src,
                                uint32_t* __restrict__ dst, int nwords) {
    int i = blockIdx.x * blockDim.x + threadIdx.x;
    if (i >= nwords) return;
    const uint4* q = (const uint4*)(src + (size_t)i * 32);
    uint32_t r = 0;
#pragma unroll
    for (int j = 0; j < 8; ++j) {
        uint4 x = q[j];
        r |= (x.x ? 1u : 0u) << (j * 4 + 0);
        r |= (x.y ? 1u : 0u) << (j * 4 + 1);
        r |= (x.z ? 1u : 0u) << (j * 4 + 2);
        r |= (x.w ? 1u : 0u) << (j * 4 + 3);
    }
    dst[i] = r;
}

__global__ void pack_conn_kernel(const int* __restrict__ conn,
                                 uint32_t* __restrict__ dst, int n) {
    int i = blockIdx.x * blockDim.x + threadIdx.x;
    if (i >= n) return;
    uint32_t v = (uint32_t)conn[i];
    // byte offset of word (v>>5) in a 32-lane replicated row (128 B/row), shift = v&31
    dst[i] = ((v & 31u) << 16) | ((v >> 5) << 7);
}

// ---------------- main recurrent kernel ----------------
__device__ __forceinline__ uint32_t lds32(uint32_t addr) {
    uint32_t v;
    asm volatile("ld.shared.b32 %0, [%1];" : "=r"(v) : "r"(addr));
    return v;
}

__device__ __forceinline__ uint32_t gstep(uint32_t a, uint32_t c, uint32_t sbase) {
    uint32_t w = lds32(sbase + (c & 0xffffu));
    return (a << 1) | ((w >> (c >> 16)) & 1u);
}

// process conn k=15..0 so bit k lands at weight 2^k (matches reference addr)
__device__ __forceinline__ uint32_t gather16(const uint4* __restrict__ cp, uint32_t sbase) {
    uint32_t a = 0;
#pragma unroll
    for (int q = 3; q >= 0; --q) {
        uint4 c = cp[q];
        a = gstep(a, c.w, sbase);
        a = gstep(a, c.z, sbase);
        a = gstep(a, c.y, sbase);
        a = gstep(a, c.x, sbase);
    }
    return a;
}

__global__ __launch_bounds__(512, 1)
void ram_main(const float* __restrict__ init_state, float* __restrict__ out) {
    // per batch-half: repA = [inp(8w) | state(8w)] x 32 lanes (replicated, bank=lane)
    //                 repB = [io(32w) | state(8w)] x 32 lanes
    __shared__ uint32_t sA[2][16][32];
    __shared__ uint32_t sB[2][40][32];

    const int tid  = threadIdx.x;
    const int h    = tid >> 8;        // which batch of this block (0/1)
    const int lane = tid & 31;
    const int w    = (tid >> 5) & 7;  // warp index within half (0..7)
    const int b    = blockIdx.x * 2 + h;

    const uint32_t sbaseA = (uint32_t)__cvta_generic_to_shared(&sA[h][0][0]) + lane * 4;
    const uint32_t sbaseB = (uint32_t)__cvta_generic_to_shared(&sB[h][0][0]) + lane * 4;

    // init state words (ballot over lanes = bit positions)
    {
        float f = init_state[b * N_ST + w * 32 + lane];
        uint32_t word = __ballot_sync(0xffffffffu, f != 0.0f);
        sA[h][8 + w][lane] = word;
        sB[h][32 + w][lane] = word;
    }
    __syncthreads();

    for (int t = 0; t < SEQ; ++t) {
        // load packed input bits for this step (broadcast load, replicate across lanes)
        sA[h][w][lane] = g_inp[((size_t)t * BATCH + b) * 8 + w];
        __syncthreads();

        // ---- phase A: input layer (1024 neurons, 32 groups of 32; warp does 4) ----
        float* outrow = out + ((size_t)t * BATCH + b) * N_IN;
#pragma unroll
        for (int gi = 0; gi < 4; ++gi) {
            int g = w + gi * 8;
            int n = g * 32 + lane;
            uint32_t a   = gather16((const uint4*)(g_connA + n * 16), sbaseA);
            uint32_t tw  = __ldg(&g_memA[n * 2048 + (a >> 5)]);
            uint32_t bit = (tw >> (a & 31u)) & 1u;
            uint32_t iow = __ballot_sync(0xffffffffu, bit != 0u);
            sB[h][g][lane] = iow;                 // replicate io word
            outrow[n] = (float)bit;               // coalesced 128B float store
        }
        __syncthreads();

        // ---- phase B: state layer (256 neurons, 8 groups; warp does 1) ----
        int m = w * 32 + lane;
        uint32_t a   = gather16((const uint4*)(g_connB + m * 16), sbaseB);
        uint32_t tw  = __ldg(&g_memB[m * 2048 + (a >> 5)]);
        uint32_t bit = (tw >> (a & 31u)) & 1u;
        uint32_t sw2 = __ballot_sync(0xffffffffu, bit != 0u);

        if (t == SEQ - 1) {
            out[(size_t)SEQ * BATCH * N_IN + b * N_ST + m] = (float)bit;
        }
        __syncthreads();            // all phase-B reads of old state done
        sA[h][8 + w][lane] = sw2;   // install new state for next step
        sB[h][32 + w][lane] = sw2;
        // next iteration's post-input-load __syncthreads makes these visible
    }
}

extern "C" void kernel_launch(void* const* d_in, const int* in_sizes, int n_in,
                              void* d_out, int out_size) {
    const float* inp        = (const float*)d_in[0];  // [128,256,256] bool->f32
    const float* init_state = (const float*)d_in[1];  // [256,256] bool->f32
    const int*   connA      = (const int*)d_in[2];    // [1024,16] int32
    const float* memA       = (const float*)d_in[3];  // [1024,65536] bool->f32
    const int*   connB      = (const int*)d_in[4];    // [256,16] int32
    const float* memB       = (const float*)d_in[5];  // [256,65536] bool->f32
    float* out = (float*)d_out;
    (void)in_sizes; (void)n_in; (void)out_size;

    uint32_t *p_inp, *p_memA, *p_memB, *p_connA, *p_connB;
    cudaGetSymbolAddress((void**)&p_inp,   g_inp);
    cudaGetSymbolAddress((void**)&p_memA,  g_memA);
    cudaGetSymbolAddress((void**)&p_memB,  g_memB);
    cudaGetSymbolAddress((void**)&p_connA, g_connA);
    cudaGetSymbolAddress((void**)&p_connB, g_connB);

    // precompute: bit-pack inputs/tables, pre-decode connections
    {
        int nw = SEQ * BATCH * 8;               // 262144
        pack_f32_kernel<<<(nw + 255) / 256, 256>>>(inp, p_inp, nw);
    }
    {
        int nw = N_IN * 2048;                   // 2097152
        pack_f32_kernel<<<(nw + 255) / 256, 256>>>(memA, p_memA, nw);
    }
    {
        int nw = N_ST * 2048;                   // 524288
        pack_f32_kernel<<<(nw + 255) / 256, 256>>>(memB, p_memB, nw);
    }
    pack_conn_kernel<<<(N_IN * 16 + 255) / 256, 256>>>(connA, p_connA, N_IN * 16);
    pack_conn_kernel<<<(N_ST * 16 + 255) / 256, 256>>>(connB, p_connB, N_ST * 16);

    // main recurrence: 128 blocks x 2 batches, fully independent per block
    ram_main<<<BATCH / 2, 512>>>(init_state, out);
}

// round 9
// speedup vs baseline: 1.5046x; 1.5046x over previous
#include <cuda_runtime.h>
#include <cstdint>

#define SEQ 128
#define BATCH 256
#define N_IN 1024
#define N_ST 256

// ---------------- static device scratch (no allocations allowed) ----------------
__device__ uint32_t g_inp[SEQ * BATCH * 8];     // packed input bits: [t][b][8 words]
__device__ uint32_t g_memA[N_IN * 2048];        // packed input-layer RAM: [n][2048 words]
__device__ uint32_t g_memB[N_ST * 2048];        // packed state-layer RAM
__device__ uint32_t g_connA[N_IN * 16];         // (shift<<16) | (word_index*32)
__device__ uint32_t g_connB[N_ST * 16];

// Pack 32 float32 {0.0,1.0} elements -> one 32-bit word (bit j = elem j != 0).
__global__ void pack_f32_kernel(const float* __restrict__ src,
                                uint32_t* __restrict__ dst, int nwords) {
    int i = blockIdx.x * blockDim.x + threadIdx.x;
    if (i >= nwords) return;
    const uint4* q = (const uint4*)(src + (size_t)i * 32);
    uint32_t r = 0;
#pragma unroll
    for (int j = 0; j < 8; ++j) {
        uint4 x = q[j];
        r |= (x.x ? 1u : 0u) << (j * 4 + 0);
        r |= (x.y ? 1u : 0u) << (j * 4 + 1);
        r |= (x.z ? 1u : 0u) << (j * 4 + 2);
        r |= (x.w ? 1u : 0u) << (j * 4 + 3);
    }
    dst[i] = r;
}

__global__ void pack_conn_kernel(const int* __restrict__ conn,
                                 uint32_t* __restrict__ dst, int n) {
    int i = blockIdx.x * blockDim.x + threadIdx.x;
    if (i >= n) return;
    uint32_t v = (uint32_t)conn[i];
    // high16 = bit shift within word; low16 = word_index*32 (row offset in
    // the lane-replicated [word][lane] shared layout). v < 1280 so fits.
    dst[i] = ((v & 31u) << 16) | (v & ~31u);
}

// ---------------- main recurrent kernel ----------------
// Plain shared-indexed gather step: compiler is free to front-batch the LDS.
__device__ __forceinline__ uint32_t gstep(uint32_t a, uint32_t c,
                                          const uint32_t* __restrict__ rep, int lane) {
    uint32_t w = rep[(c & 0xffffu) + lane];
    return (a + a) | ((w >> (c >> 16)) & 1u);
}

// 16-bit gather; k = 15..0 so conn bit k gets weight 2^k (matches reference).
__device__ __forceinline__ uint32_t gather16(const uint32_t* __restrict__ cw,
                                             const uint32_t* __restrict__ rep, int lane) {
    uint32_t a = 0;
#pragma unroll
    for (int k = 15; k >= 0; --k) a = gstep(a, cw[k], rep, lane);
    return a;
}

__global__ __launch_bounds__(256, 2)
void ram_main(const float* __restrict__ init_state, float* __restrict__ out) {
    // Lane-replicated bit vectors (bank == lane -> conflict-free gathers):
    //   sA = [inp(8 words) | state(8 words)]   rows x 32 lanes
    //   sB = [io(32 words) | state(8 words)]   rows x 32 lanes
    __shared__ uint32_t sA[16 * 32];
    __shared__ uint32_t sB[40 * 32];

    const int tid  = threadIdx.x;
    const int lane = tid & 31;
    const int w    = tid >> 5;          // warp 0..7
    const int b    = blockIdx.x;        // one batch per block

    // init state words (ballot over lanes = bit positions)
    {
        float f = init_state[b * N_ST + w * 32 + lane];
        uint32_t word = __ballot_sync(0xffffffffu, f != 0.0f);
        sA[(8 + w) * 32 + lane]  = word;
        sB[(32 + w) * 32 + lane] = word;
    }

    for (int t = 0; t < SEQ; ++t) {
        // packed input bits for this step (broadcast load, replicated across lanes)
        sA[w * 32 + lane] = g_inp[((size_t)t * BATCH + b) * 8 + w];
        __syncthreads();   // input + (installed) state visible

        // ---- phase A: 1024 neurons; warp w handles groups w*4 .. w*4+3 ----
        float* outrow = out + ((size_t)t * BATCH + b) * N_IN;
        uint32_t acc[4], tw[4];
#pragma unroll
        for (int gi = 0; gi < 4; ++gi) {
            int n = (w * 4 + gi) * 32 + lane;
            uint32_t cw[16];
#pragma unroll
            for (int k = 0; k < 16; ++k) cw[k] = __ldg(&g_connA[n * 16 + k]);
            acc[gi] = gather16(cw, sA, lane);
        }
#pragma unroll
        for (int gi = 0; gi < 4; ++gi) {   // 4 table lookups in flight (L2-only)
            int n = (w * 4 + gi) * 32 + lane;
            tw[gi] = __ldcg(&g_memA[n * 2048 + (acc[gi] >> 5)]);
        }
#pragma unroll
        for (int gi = 0; gi < 4; ++gi) {
            int g = w * 4 + gi;
            uint32_t bit = (tw[gi] >> (acc[gi] & 31u)) & 1u;
            uint32_t iow = __ballot_sync(0xffffffffu, bit != 0u);
            sB[g * 32 + lane] = iow;                  // replicate io word
            outrow[g * 32 + lane] = (float)bit;       // coalesced 128B store
        }
        __syncthreads();   // io words visible

        // ---- phase B: 256 neurons; warp w handles neurons w*32 .. w*32+31 ----
        int m = w * 32 + lane;
        uint32_t cw[16];
#pragma unroll
        for (int k = 0; k < 16; ++k) cw[k] = __ldg(&g_connB[m * 16 + k]);
        uint32_t a   = gather16(cw, sB, lane);
        uint32_t twb = __ldcg(&g_memB[m * 2048 + (a >> 5)]);
        uint32_t bit = (twb >> (a & 31u)) & 1u;
        uint32_t sw2 = __ballot_sync(0xffffffffu, bit != 0u);

        if (t == SEQ - 1) {
            out[(size_t)SEQ * BATCH * N_IN + b * N_ST + m] = (float)bit;
        }
        __syncthreads();   // all phase-B reads of old state done
        sA[(8 + w) * 32 + lane]  = sw2;    // install new state
        sB[(32 + w) * 32 + lane] = sw2;
        // next iteration's first __syncthreads makes these visible
    }
}

extern "C" void kernel_launch(void* const* d_in, const int* in_sizes, int n_in,
                              void* d_out, int out_size) {
    const float* inp        = (const float*)d_in[0];  // [128,256,256] bool->f32
    const float* init_state = (const float*)d_in[1];  // [256,256] bool->f32
    const int*   connA      = (const int*)d_in[2];    // [1024,16] int32
    const float* memA       = (const float*)d_in[3];  // [1024,65536] bool->f32
    const int*   connB      = (const int*)d_in[4];    // [256,16] int32
    const float* memB       = (const float*)d_in[5];  // [256,65536] bool->f32
    float* out = (float*)d_out;
    (void)in_sizes; (void)n_in; (void)out_size;

    uint32_t *p_inp, *p_memA, *p_memB, *p_connA, *p_connB;
    cudaGetSymbolAddress((void**)&p_inp,   g_inp);
    cudaGetSymbolAddress((void**)&p_memA,  g_memA);
    cudaGetSymbolAddress((void**)&p_memB,  g_memB);
    cudaGetSymbolAddress((void**)&p_connA, g_connA);
    cudaGetSymbolAddress((void**)&p_connB, g_connB);

    // precompute: bit-pack inputs/tables, pre-decode connections
    {
        int nw = SEQ * BATCH * 8;               // 262144
        pack_f32_kernel<<<(nw + 255) / 256, 256>>>(inp, p_inp, nw);
    }
    {
        int nw = N_IN * 2048;                   // 2097152
        pack_f32_kernel<<<(nw + 255) / 256, 256>>>(memA, p_memA, nw);
    }
    {
        int nw = N_ST * 2048;                   // 524288
        pack_f32_kernel<<<(nw + 255) / 256, 256>>>(memB, p_memB, nw);
    }
    pack_conn_kernel<<<(N_IN * 16 + 255) / 256, 256>>>(connA, p_connA, N_IN * 16);
    pack_conn_kernel<<<(N_ST * 16 + 255) / 256, 256>>>(connB, p_connB, N_ST * 16);

    // main recurrence: 256 blocks, one independent batch chain each
    ram_main<<<BATCH, 256>>>(init_state, out);
}

// round 10
// speedup vs baseline: 1.5114x; 1.0045x over previous
#include <cuda_runtime.h>
#include <cstdint>

#define SEQ 128
#define BATCH 256
#define N_IN 1024
#define N_ST 256

// ---------------- static device scratch (no allocations allowed) ----------------
__device__ uint32_t g_inp[SEQ * BATCH * 8];     // packed input bits: [t][b][8 words]
__device__ uint32_t g_memA[N_IN * 2048];        // packed input-layer RAM: [n][2048 words]
__device__ uint32_t g_memB[N_ST * 2048];        // packed state-layer RAM
__device__ uint32_t g_connA[N_IN * 16];         // (shift<<16) | (word_index*32)
__device__ uint32_t g_connB[N_ST * 16];

// Pack 32 float32 {0.0,1.0} elements -> one 32-bit word (bit j = elem j != 0).
__global__ void pack_f32_kernel(const float* __restrict__ src,
                                uint32_t* __restrict__ dst, int nwords) {
    int i = blockIdx.x * blockDim.x + threadIdx.x;
    if (i >= nwords) return;
    const uint4* q = (const uint4*)(src + (size_t)i * 32);
    uint32_t r = 0;
#pragma unroll
    for (int j = 0; j < 8; ++j) {
        uint4 x = q[j];
        r |= (x.x ? 1u : 0u) << (j * 4 + 0);
        r |= (x.y ? 1u : 0u) << (j * 4 + 1);
        r |= (x.z ? 1u : 0u) << (j * 4 + 2);
        r |= (x.w ? 1u : 0u) << (j * 4 + 3);
    }
    dst[i] = r;
}

__global__ void pack_conn_kernel(const int* __restrict__ conn,
                                 uint32_t* __restrict__ dst, int n) {
    int i = blockIdx.x * blockDim.x + threadIdx.x;
    if (i >= n) return;
    uint32_t v = (uint32_t)conn[i];
    // high16 = bit shift within word; low16 = word_index*32 (row offset in
    // the lane-replicated [word][lane] shared layout). v < 1280 so fits.
    dst[i] = ((v & 31u) << 16) | (v & ~31u);
}

// ---------------- main recurrent kernel ----------------
// Plain shared-indexed gather step: compiler is free to front-batch the LDS.
__device__ __forceinline__ uint32_t gstep(uint32_t a, uint32_t c,
                                          const uint32_t* __restrict__ rep, int lane) {
    uint32_t w = rep[(c & 0xffffu) + lane];
    return (a + a) | ((w >> (c >> 16)) & 1u);
}

// 16-bit gather; k = 15..0 so conn bit k gets weight 2^k (matches reference).
__device__ __forceinline__ uint32_t gather16(const uint32_t* __restrict__ cw,
                                             const uint32_t* __restrict__ rep, int lane) {
    uint32_t a = 0;
#pragma unroll
    for (int k = 15; k >= 0; --k) a = gstep(a, cw[k], rep, lane);
    return a;
}

__global__ __launch_bounds__(256, 2)
void ram_main(const float* __restrict__ init_state, float* __restrict__ out) {
    // Lane-replicated bit vectors (bank == lane -> conflict-free gathers):
    //   sA = [inp(8 words) | state(8 words)]   rows x 32 lanes
    //   sB = [io(32 words) | state(8 words)]   rows x 32 lanes
    __shared__ uint32_t sA[16 * 32];
    __shared__ uint32_t sB[40 * 32];

    const int tid  = threadIdx.x;
    const int lane = tid & 31;
    const int w    = tid >> 5;          // warp 0..7
    const int b    = blockIdx.x;        // one batch per block

    // init state words (ballot over lanes = bit positions)
    {
        float f = init_state[b * N_ST + w * 32 + lane];
        uint32_t word = __ballot_sync(0xffffffffu, f != 0.0f);
        sA[(8 + w) * 32 + lane]  = word;
        sB[(32 + w) * 32 + lane] = word;
    }

    for (int t = 0; t < SEQ; ++t) {
        // packed input bits for this step (broadcast load, replicated across lanes)
        sA[w * 32 + lane] = g_inp[((size_t)t * BATCH + b) * 8 + w];
        __syncthreads();   // input + (installed) state visible

        // ---- phase A: 1024 neurons; warp w handles groups w*4 .. w*4+3 ----
        float* outrow = out + ((size_t)t * BATCH + b) * N_IN;
        uint32_t acc[4], tw[4];
#pragma unroll
        for (int gi = 0; gi < 4; ++gi) {
            int n = (w * 4 + gi) * 32 + lane;
            uint32_t cw[16];
#pragma unroll
            for (int k = 0; k < 16; ++k) cw[k] = __ldg(&g_connA[n * 16 + k]);
            acc[gi] = gather16(cw, sA, lane);
        }
#pragma unroll
        for (int gi = 0; gi < 4; ++gi) {   // 4 table lookups in flight (L2-only)
            int n = (w * 4 + gi) * 32 + lane;
            tw[gi] = __ldcg(&g_memA[n * 2048 + (acc[gi] >> 5)]);
        }
#pragma unroll
        for (int gi = 0; gi < 4; ++gi) {
            int g = w * 4 + gi;
            uint32_t bit = (tw[gi] >> (acc[gi] & 31u)) & 1u;
            uint32_t iow = __ballot_sync(0xffffffffu, bit != 0u);
            sB[g * 32 + lane] = iow;                  // replicate io word
            outrow[g * 32 + lane] = (float)bit;       // coalesced 128B store
        }
        __syncthreads();   // io words visible

        // ---- phase B: 256 neurons; warp w handles neurons w*32 .. w*32+31 ----
        int m = w * 32 + lane;
        uint32_t cw[16];
#pragma unroll
        for (int k = 0; k < 16; ++k) cw[k] = __ldg(&g_connB[m * 16 + k]);
        uint32_t a   = gather16(cw, sB, lane);
        uint32_t twb = __ldcg(&g_memB[m * 2048 + (a >> 5)]);
        uint32_t bit = (twb >> (a & 31u)) & 1u;
        uint32_t sw2 = __ballot_sync(0xffffffffu, bit != 0u);

        if (t == SEQ - 1) {
            out[(size_t)SEQ * BATCH * N_IN + b * N_ST + m] = (float)bit;
        }
        __syncthreads();   // all phase-B reads of old state done
        sA[(8 + w) * 32 + lane]  = sw2;    // install new state
        sB[(32 + w) * 32 + lane] = sw2;
        // next iteration's first __syncthreads makes these visible
    }
}

extern "C" void kernel_launch(void* const* d_in, const int* in_sizes, int n_in,
                              void* d_out, int out_size) {
    const float* inp        = (const float*)d_in[0];  // [128,256,256] bool->f32
    const float* init_state = (const float*)d_in[1];  // [256,256] bool->f32
    const int*   connA      = (const int*)d_in[2];    // [1024,16] int32
    const float* memA       = (const float*)d_in[3];  // [1024,65536] bool->f32
    const int*   connB      = (const int*)d_in[4];    // [256,16] int32
    const float* memB       = (const float*)d_in[5];  // [256,65536] bool->f32
    float* out = (float*)d_out;
    (void)in_sizes; (void)n_in; (void)out_size;

    uint32_t *p_inp, *p_memA, *p_memB, *p_connA, *p_connB;
    cudaGetSymbolAddress((void**)&p_inp,   g_inp);
    cudaGetSymbolAddress((void**)&p_memA,  g_memA);
    cudaGetSymbolAddress((void**)&p_memB,  g_memB);
    cudaGetSymbolAddress((void**)&p_connA, g_connA);
    cudaGetSymbolAddress((void**)&p_connB, g_connB);

    // precompute: bit-pack inputs/tables, pre-decode connections
    {
        int nw = SEQ * BATCH * 8;               // 262144
        pack_f32_kernel<<<(nw + 255) / 256, 256>>>(inp, p_inp, nw);
    }
    {
        int nw = N_IN * 2048;                   // 2097152
        pack_f32_kernel<<<(nw + 255) / 256, 256>>>(memA, p_memA, nw);
    }
    {
        int nw = N_ST * 2048;                   // 524288
        pack_f32_kernel<<<(nw + 255) / 256, 256>>>(memB, p_memB, nw);
    }
    pack_conn_kernel<<<(N_IN * 16 + 255) / 256, 256>>>(connA, p_connA, N_IN * 16);
    pack_conn_kernel<<<(N_ST * 16 + 255) / 256, 256>>>(connB, p_connB, N_ST * 16);

    // main recurrence: 256 blocks, one independent batch chain each
    ram_main<<<BATCH, 256>>>(init_state, out);
}

// round 11
// speedup vs baseline: 1.6803x; 1.1117x over previous
#include <cuda_runtime.h>
#include <cstdint>

#define SEQ 128
#define BATCH 256
#define N_IN 1024
#define N_ST 256

// ---------------- static device scratch (no allocations allowed) ----------------
__device__ uint32_t g_inp[SEQ * BATCH * 8];     // packed input bits: [t][b][8 words]
__device__ uint32_t g_memA[N_IN * 2048];        // packed input-layer RAM: [n][2048 words]
__device__ uint32_t g_memB[N_ST * 2048];        // packed state-layer RAM
__device__ uint32_t g_connA[N_IN * 16];         // (shift<<16) | (row_word_offset)
__device__ uint32_t g_connB[N_ST * 16];

// Pack 32 float32 {0.0,1.0} elements -> one 32-bit word (bit j = elem j != 0).
__global__ void pack_f32_kernel(const float* __restrict__ src,
                                uint32_t* __restrict__ dst, int nwords) {
    int i = blockIdx.x * blockDim.x + threadIdx.x;
    if (i >= nwords) return;
    const uint4* q = (const uint4*)(src + (size_t)i * 32);
    uint32_t r = 0;
#pragma unroll
    for (int j = 0; j < 8; ++j) {
        uint4 x = q[j];
        r |= (x.x ? 1u : 0u) << (j * 4 + 0);
        r |= (x.y ? 1u : 0u) << (j * 4 + 1);
        r |= (x.z ? 1u : 0u) << (j * 4 + 2);
        r |= (x.w ? 1u : 0u) << (j * 4 + 3);
    }
    dst[i] = r;
}

// Unified layout U (48 rows x 32 lanes): rows 0-7 inp, 8-15 state, 16-47 io.
// connA positions p in [0,512): [inp|state] -> row = p>>5 directly.
__global__ void pack_connA_kernel(const int* __restrict__ conn,
                                  uint32_t* __restrict__ dst, int n) {
    int i = blockIdx.x * blockDim.x + threadIdx.x;
    if (i >= n) return;
    uint32_t v = (uint32_t)conn[i];
    dst[i] = ((v & 31u) << 16) | ((v >> 5) * 32u);
}

// connB positions p in [0,1280): [io(1024)|state(256)]
//   p < 1024 -> io row 16 + (p>>5);  p >= 1024 -> state row (p>>5) - 24.
__global__ void pack_connB_kernel(const int* __restrict__ conn,
                                  uint32_t* __restrict__ dst, int n) {
    int i = blockIdx.x * blockDim.x + threadIdx.x;
    if (i >= n) return;
    uint32_t v = (uint32_t)conn[i];
    uint32_t row = (v < 1024u) ? (16u + (v >> 5)) : ((v >> 5) - 24u);
    dst[i] = ((v & 31u) << 16) | (row * 32u);
}

// ---------------- main recurrent kernel ----------------
// One gather step; conn word comes from a register, compiler front-batches LDS.
__device__ __forceinline__ uint32_t gstep(uint32_t a, uint32_t c,
                                          const uint32_t* __restrict__ rep, int lane) {
    uint32_t w = rep[(c & 0xffffu) + lane];
    return (a + a) | ((w >> (c >> 16)) & 1u);
}

__device__ __forceinline__ uint32_t gather16(const uint32_t* __restrict__ cw,
                                             const uint32_t* __restrict__ rep, int lane) {
    uint32_t a = 0;
#pragma unroll
    for (int k = 15; k >= 0; --k) a = gstep(a, cw[k], rep, lane);
    return a;
}

__global__ __launch_bounds__(256, 2)
void ram_main(const float* __restrict__ init_state, float* __restrict__ out) {
    // Ping-ponged lane-replicated bit vectors (bank == lane -> conflict-free).
    __shared__ uint32_t U[2][48 * 32];

    const int tid  = threadIdx.x;
    const int lane = tid & 31;
    const int w    = tid >> 5;          // warp 0..7
    const int b    = blockIdx.x;        // one batch per block

    // Hoist loop-invariant connections into registers (64 + 16 words).
    uint32_t cA[64], cB[16];
#pragma unroll
    for (int gi = 0; gi < 4; ++gi) {
        int n = (w * 4 + gi) * 32 + lane;
#pragma unroll
        for (int k = 0; k < 16; ++k) cA[gi * 16 + k] = g_connA[n * 16 + k];
    }
    {
        int m = w * 32 + lane;
#pragma unroll
        for (int k = 0; k < 16; ++k) cB[k] = g_connB[m * 16 + k];
    }

    // init state words into copy 0 (used by step 0)
    {
        float f = init_state[b * N_ST + w * 32 + lane];
        uint32_t word = __ballot_sync(0xffffffffu, f != 0.0f);
        U[0][(8 + w) * 32 + lane] = word;
    }

    for (int t = 0; t < SEQ; ++t) {
        uint32_t* cur = U[t & 1];
        uint32_t* nxt = U[(t + 1) & 1];

        // packed input bits for this step (broadcast load, replicated to lanes)
        cur[w * 32 + lane] = g_inp[((size_t)t * BATCH + b) * 8 + w];
        __syncthreads();   // input + previously installed state visible

        // ---- phase A: 1024 neurons; warp w handles groups w*4 .. w*4+3 ----
        float* outrow = out + ((size_t)t * BATCH + b) * N_IN;
        uint32_t acc[4], tw[4];
#pragma unroll
        for (int gi = 0; gi < 4; ++gi)
            acc[gi] = gather16(&cA[gi * 16], cur, lane);
#pragma unroll
        for (int gi = 0; gi < 4; ++gi) {   // 4 table lookups in flight (L2)
            int n = (w * 4 + gi) * 32 + lane;
            tw[gi] = __ldcg(&g_memA[n * 2048 + (acc[gi] >> 5)]);
        }
#pragma unroll
        for (int gi = 0; gi < 4; ++gi) {
            int g = w * 4 + gi;
            uint32_t bit = (tw[gi] >> (acc[gi] & 31u)) & 1u;
            uint32_t iow = __ballot_sync(0xffffffffu, bit != 0u);
            cur[(16 + g) * 32 + lane] = iow;          // replicate io word
            outrow[g * 32 + lane] = (float)bit;       // coalesced 128B store
        }
        __syncthreads();   // io words visible

        // ---- phase B: 256 neurons; warp w handles neurons w*32 .. w*32+31 ----
        int m = w * 32 + lane;
        uint32_t a   = gather16(cB, cur, lane);
        uint32_t twb = __ldcg(&g_memB[m * 2048 + (a >> 5)]);
        uint32_t bit = (twb >> (a & 31u)) & 1u;
        uint32_t sw2 = __ballot_sync(0xffffffffu, bit != 0u);

        if (t == SEQ - 1) {
            out[(size_t)SEQ * BATCH * N_IN + b * N_ST + m] = (float)bit;
        }
        // Install next state into the OTHER copy: no barrier needed here.
        // All warps already passed this step's barriers, so nobody is still
        // reading the previous contents of these rows; readers of the new
        // state sync on the next iteration's __syncthreads().
        nxt[(8 + w) * 32 + lane] = sw2;
    }
}

extern "C" void kernel_launch(void* const* d_in, const int* in_sizes, int n_in,
                              void* d_out, int out_size) {
    const float* inp        = (const float*)d_in[0];  // [128,256,256] bool->f32
    const float* init_state = (const float*)d_in[1];  // [256,256] bool->f32
    const int*   connA      = (const int*)d_in[2];    // [1024,16] int32
    const float* memA       = (const float*)d_in[3];  // [1024,65536] bool->f32
    const int*   connB      = (const int*)d_in[4];    // [256,16] int32
    const float* memB       = (const float*)d_in[5];  // [256,65536] bool->f32
    float* out = (float*)d_out;
    (void)in_sizes; (void)n_in; (void)out_size;

    uint32_t *p_inp, *p_memA, *p_memB, *p_connA, *p_connB;
    cudaGetSymbolAddress((void**)&p_inp,   g_inp);
    cudaGetSymbolAddress((void**)&p_memA,  g_memA);
    cudaGetSymbolAddress((void**)&p_memB,  g_memB);
    cudaGetSymbolAddress((void**)&p_connA, g_connA);
    cudaGetSymbolAddress((void**)&p_connB, g_connB);

    // precompute: bit-pack inputs/tables, pre-decode connections
    {
        int nw = SEQ * BATCH * 8;               // 262144
        pack_f32_kernel<<<(nw + 255) / 256, 256>>>(inp, p_inp, nw);
    }
    {
        int nw = N_IN * 2048;                   // 2097152
        pack_f32_kernel<<<(nw + 255) / 256, 256>>>(memA, p_memA, nw);
    }
    {
        int nw = N_ST * 2048;                   // 524288
        pack_f32_kernel<<<(nw + 255) / 256, 256>>>(memB, p_memB, nw);
    }
    pack_connA_kernel<<<(N_IN * 16 + 255) / 256, 256>>>(connA, p_connA, N_IN * 16);
    pack_connB_kernel<<<(N_ST * 16 + 255) / 256, 256>>>(connB, p_connB, N_ST * 16);

    // main recurrence: 256 blocks, one independent batch chain each
    ram_main<<<BATCH, 256>>>(init_state, out);
}